// round 5
// baseline (speedup 1.0000x reference)
#include <cuda_runtime.h>
#include <cuda_bf16.h>

// ---------------- problem constants ----------------
#define NN    65536
#define HIDD  256
#define BB    64
#define EPER  8192
#define ET    524288
#define NRES  4096
#define EC    262144

// ---------------- output offsets (float32 elements) ----------------
#define OFF_CX   0ul
#define OFF_CEI  16777216ul
#define OFF_CW   17301504ul
#define OFF_CB   17563648ul
#define OFF_FX   17629184ul
#define OFF_FEI  34406400ul
#define OFF_FW   34930688ul
#define OFF_FB   35192832ul
#define OFF_ES   35258368ul

// ---------------- scratch (zero-initialized at module load) ----------------
__device__ float g_t[NN * HIDD];
__device__ float g_u[NN * HIDD];
__device__ float g_h[NN * HIDD];
__device__ int   g_deg[NN + 1];   // 0 at entry; re-zeroed at tail
__device__ int   g_pos[NN];
__device__ int   g_col[ET];
__device__ float g_ssrc[NN];
__device__ float g_sdst[NN];
__device__ int   g_cei[2 * EC];
__device__ int   g_fei[2 * EC];
__device__ int   g_pres_c[NN];    // 0 at entry; re-zeroed at tail
__device__ int   g_pres_f[NN];
__device__ int   g_rank_c[NN];
__device__ int   g_rank_f[NN];
__device__ int   g_list_c[NN];
__device__ int   g_list_f[NN];
__device__ int   g_cnt_c;
__device__ int   g_cnt_f;

// ---------------- CSR build ----------------
__global__ void k_count_deg(const int* __restrict__ ei) {
    int e = blockIdx.x * blockDim.x + threadIdx.x;
    if (e < ET) atomicAdd(&g_deg[ei[e] + 1], 1);
}

__global__ __launch_bounds__(1024) void k_scan_deg() {
    __shared__ int part[1024];
    const int t = threadIdx.x;
    const int CH = 65;
    int base = t * CH;
    int n = 0;
    if (base < NN + 1) { n = NN + 1 - base; if (n > CH) n = CH; }
    int s = 0;
    for (int i = 0; i < n; i++) s += g_deg[base + i];
    part[t] = s;
    __syncthreads();
    for (int off = 1; off < 1024; off <<= 1) {
        int v = (t >= off) ? part[t - off] : 0;
        __syncthreads();
        part[t] += v;
        __syncthreads();
    }
    int run = part[t] - s;
    for (int i = 0; i < n; i++) {
        run += g_deg[base + i];
        g_deg[base + i] = run;
        if (base + i < NN) g_pos[base + i] = run;
    }
}

__global__ void k_fill_csr(const int* __restrict__ ei) {
    int e = blockIdx.x * blockDim.x + threadIdx.x;
    if (e < ET) {
        int r = ei[e];
        int p = atomicAdd(&g_pos[r], 1);
        g_col[p] = ei[ET + e];
    }
}

// ---------------- aggregation: warp-per-node, shfl-broadcast cols ----------------
// t[v] = h[v] + sum_nb h[nb]; lane covers 8 floats (2 float4s).
__global__ __launch_bounds__(256) void k_agg(const float* __restrict__ hin,
                                             float* __restrict__ tout) {
    int v = (blockIdx.x * blockDim.x + threadIdx.x) >> 5;
    int lane = threadIdx.x & 31;
    const float4* H = (const float4*)hin;
    const int i0 = lane * 2;
    float4 a0 = H[(size_t)v * 64 + i0];
    float4 a1 = H[(size_t)v * 64 + i0 + 1];
    int s = g_deg[v], e = g_deg[v + 1];

    for (int base = s; base < e; base += 32) {
        int rem = e - base; if (rem > 32) rem = 32;
        int my = (lane < rem) ? g_col[base + lane] : 0;
        int j = 0;
        for (; j + 4 <= rem; j += 4) {
            int n0 = __shfl_sync(0xffffffffu, my, j);
            int n1 = __shfl_sync(0xffffffffu, my, j + 1);
            int n2 = __shfl_sync(0xffffffffu, my, j + 2);
            int n3 = __shfl_sync(0xffffffffu, my, j + 3);
            float4 x0 = H[(size_t)n0 * 64 + i0], y0 = H[(size_t)n0 * 64 + i0 + 1];
            float4 x1 = H[(size_t)n1 * 64 + i0], y1 = H[(size_t)n1 * 64 + i0 + 1];
            float4 x2 = H[(size_t)n2 * 64 + i0], y2 = H[(size_t)n2 * 64 + i0 + 1];
            float4 x3 = H[(size_t)n3 * 64 + i0], y3 = H[(size_t)n3 * 64 + i0 + 1];
            a0.x += x0.x + x1.x + x2.x + x3.x;
            a0.y += x0.y + x1.y + x2.y + x3.y;
            a0.z += x0.z + x1.z + x2.z + x3.z;
            a0.w += x0.w + x1.w + x2.w + x3.w;
            a1.x += y0.x + y1.x + y2.x + y3.x;
            a1.y += y0.y + y1.y + y2.y + y3.y;
            a1.z += y0.z + y1.z + y2.z + y3.z;
            a1.w += y0.w + y1.w + y2.w + y3.w;
        }
        for (; j < rem; j++) {
            int nb = __shfl_sync(0xffffffffu, my, j);
            float4 x = H[(size_t)nb * 64 + i0], y = H[(size_t)nb * 64 + i0 + 1];
            a0.x += x.x; a0.y += x.y; a0.z += x.z; a0.w += x.w;
            a1.x += y.x; a1.y += y.y; a1.z += y.z; a1.w += y.w;
        }
    }
    ((float4*)tout)[(size_t)v * 64 + i0] = a0;
    ((float4*)tout)[(size_t)v * 64 + i0 + 1] = a1;
}

// ---------------- GEMM: C = relu(A @ W + bias) ----------------
// Canonical SIMT SGEMM: 128x128 tile, BK=8, 256 threads, 8x8 micro-tile,
// double-buffered smem, plain FFMA (no f32x2 asm), 2 CTAs/SM.
#define BM 128
#define BN 128
#define BK 8

__global__ __launch_bounds__(256, 2) void k_gemm_bias_relu(const float* __restrict__ A,
                                                           const float* __restrict__ W,
                                                           const float* __restrict__ bias,
                                                           float* __restrict__ C) {
    __shared__ float As[2][BK][BM];   // transposed A tile
    __shared__ float Bs[2][BK][BN];

    const int t  = threadIdx.x;
    const int bm = blockIdx.x;
    const int bn = blockIdx.y;
    const int a_row = t >> 1,  a_k   = (t & 1) * 4;
    const int b_row = t >> 5,  b_col = (t & 31) * 4;
    const int tx = t & 15, ty = t >> 4;

    const float* Ab = A + (size_t)bm * BM * 256;
    const float* Wb = W + bn * BN;

    float acc[8][8];
#pragma unroll
    for (int m = 0; m < 8; m++)
#pragma unroll
        for (int n = 0; n < 8; n++) acc[m][n] = 0.f;

    float4 ra = *(const float4*)&Ab[(size_t)a_row * 256 + a_k];
    float4 rb = *(const float4*)&Wb[(size_t)b_row * 256 + b_col];
    As[0][a_k + 0][a_row] = ra.x;
    As[0][a_k + 1][a_row] = ra.y;
    As[0][a_k + 2][a_row] = ra.z;
    As[0][a_k + 3][a_row] = ra.w;
    *(float4*)&Bs[0][b_row][b_col] = rb;
    __syncthreads();

    for (int kt = 0; kt < 32; kt++) {
        const int cur = kt & 1, nxt = cur ^ 1;
        if (kt < 31) {
            int k0 = (kt + 1) * BK;
            ra = *(const float4*)&Ab[(size_t)a_row * 256 + k0 + a_k];
            rb = *(const float4*)&Wb[(size_t)(k0 + b_row) * 256 + b_col];
        }
#pragma unroll
        for (int k = 0; k < BK; k++) {
            float4 a0 = *(const float4*)&As[cur][k][ty * 4];
            float4 a1 = *(const float4*)&As[cur][k][64 + ty * 4];
            float4 b0 = *(const float4*)&Bs[cur][k][tx * 4];
            float4 b1 = *(const float4*)&Bs[cur][k][64 + tx * 4];
            float av[8] = {a0.x, a0.y, a0.z, a0.w, a1.x, a1.y, a1.z, a1.w};
            float bv[8] = {b0.x, b0.y, b0.z, b0.w, b1.x, b1.y, b1.z, b1.w};
#pragma unroll
            for (int m = 0; m < 8; m++)
#pragma unroll
                for (int n = 0; n < 8; n++) acc[m][n] += av[m] * bv[n];
        }
        if (kt < 31) {
            As[nxt][a_k + 0][a_row] = ra.x;
            As[nxt][a_k + 1][a_row] = ra.y;
            As[nxt][a_k + 2][a_row] = ra.z;
            As[nxt][a_k + 3][a_row] = ra.w;
            *(float4*)&Bs[nxt][b_row][b_col] = rb;
        }
        __syncthreads();
    }

    float4 bv0 = *(const float4*)&bias[bn * BN + tx * 4];
    float4 bv1 = *(const float4*)&bias[bn * BN + 64 + tx * 4];
#pragma unroll
    for (int m = 0; m < 8; m++) {
        int row = bm * BM + ((m < 4) ? (ty * 4 + m) : (64 + ty * 4 + m - 4));
        float4 r0, r1;
        r0.x = fmaxf(acc[m][0] + bv0.x, 0.f);
        r0.y = fmaxf(acc[m][1] + bv0.y, 0.f);
        r0.z = fmaxf(acc[m][2] + bv0.z, 0.f);
        r0.w = fmaxf(acc[m][3] + bv0.w, 0.f);
        r1.x = fmaxf(acc[m][4] + bv1.x, 0.f);
        r1.y = fmaxf(acc[m][5] + bv1.y, 0.f);
        r1.z = fmaxf(acc[m][6] + bv1.z, 0.f);
        r1.w = fmaxf(acc[m][7] + bv1.w, 0.f);
        *(float4*)&C[(size_t)row * 256 + bn * BN + tx * 4] = r0;
        *(float4*)&C[(size_t)row * 256 + bn * BN + 64 + tx * 4] = r1;
    }
}

// ---------------- scores ----------------
__global__ __launch_bounds__(256) void k_score(const float* __restrict__ h,
                                               const float* __restrict__ wsc) {
    int gw = (blockIdx.x * blockDim.x + threadIdx.x) >> 5;
    int lane = threadIdx.x & 31;
    if (gw >= NN) return;
    const float4* H = (const float4*)(h + (size_t)gw * 256);
    const float4* W1 = (const float4*)wsc;
    const float4* W2 = (const float4*)(wsc + 256);
    float s1 = 0.f, s2 = 0.f;
#pragma unroll
    for (int i = lane; i < 64; i += 32) {
        float4 hv = H[i], w1 = W1[i], w2 = W2[i];
        s1 += hv.x * w1.x + hv.y * w1.y + hv.z * w1.z + hv.w * w1.w;
        s2 += hv.x * w2.x + hv.y * w2.y + hv.z * w2.z + hv.w * w2.w;
    }
#pragma unroll
    for (int o = 16; o; o >>= 1) {
        s1 += __shfl_xor_sync(0xffffffffu, s1, o);
        s2 += __shfl_xor_sync(0xffffffffu, s2, o);
    }
    if (lane == 0) { g_ssrc[gw] = s1; g_sdst[gw] = s2; }
}

__global__ void k_edge_score(const int* __restrict__ ei,
                             const float* __restrict__ bsc,
                             float* __restrict__ out) {
    int e = blockIdx.x * blockDim.x + threadIdx.x;
    if (e < ET) {
        out[OFF_ES + e] = g_ssrc[ei[e]] + g_sdst[ei[ET + e]] + bsc[0];
    }
}

// ---------------- per-batch stable sort + split ----------------
__global__ __launch_bounds__(1024) void k_sort_select(const float* __restrict__ es,
                                                      const int* __restrict__ ei,
                                                      float* __restrict__ out) {
    __shared__ unsigned int   kh[EPER];
    __shared__ unsigned short kl[EPER];
    const int b = blockIdx.x;
    const int tid = threadIdx.x;

    for (int i = tid; i < EPER; i += 1024) {
        float s = es[b * EPER + i];
        unsigned u = __float_as_uint(s);
        u = (u & 0x80000000u) ? ~u : (u | 0x80000000u);
        kh[i] = ~u;
        kl[i] = (unsigned short)i;
    }
    __syncthreads();

    for (int k = 2; k <= EPER; k <<= 1) {
        for (int j = k >> 1; j > 0; j >>= 1) {
            for (int i = tid; i < EPER; i += 1024) {
                int l = i ^ j;
                if (l > i) {
                    bool up = ((i & k) == 0);
                    unsigned ah = kh[i], bh = kh[l];
                    unsigned short al = kl[i], bl = kl[l];
                    bool agtb = (ah > bh) || (ah == bh && al > bl);
                    if (agtb == up) {
                        kh[i] = bh; kh[l] = ah;
                        kl[i] = bl; kl[l] = al;
                    }
                }
            }
            __syncthreads();
        }
    }

    for (int i = tid; i < EPER; i += 1024) {
        int idx = kl[i];
        int ge = b * EPER + idx;
        float s = es[ge];
        int r = ei[ge];
        int c = ei[ET + ge];
        if (i < NRES) {
            int p = b * NRES + i;
            out[OFF_CW + p] = s;
            g_cei[p] = r; g_cei[EC + p] = c;
            g_pres_c[r] = 1; g_pres_c[c] = 1;
        } else {
            int p = b * NRES + (i - NRES);
            out[OFF_FW + p] = -s;
            g_fei[p] = r; g_fei[EC + p] = c;
            g_pres_f[r] = 1; g_pres_f[c] = 1;
        }
    }
}

// ---------------- relabel: compact + batch fill ----------------
__global__ __launch_bounds__(1024) void k_compact(const int* __restrict__ batch_in,
                                                  float* __restrict__ out) {
    __shared__ int part[1024];
    const int which = blockIdx.x;
    const int* pres = which ? g_pres_f : g_pres_c;
    int* rank = which ? g_rank_f : g_rank_c;
    int* list = which ? g_list_f : g_list_c;
    int* cnt = which ? &g_cnt_f : &g_cnt_c;
    float* out_b = out + (which ? OFF_FB : OFF_CB);

    const int t = threadIdx.x;
    const int base = t * 64;
    int s = 0;
    for (int i = 0; i < 64; i++) s += pres[base + i];
    part[t] = s;
    __syncthreads();
    for (int off = 1; off < 1024; off <<= 1) {
        int v = (t >= off) ? part[t - off] : 0;
        __syncthreads();
        part[t] += v;
        __syncthreads();
    }
    int total = part[1023];
    int run = part[t] - s;
    for (int i = 0; i < 64; i++) {
        int v = base + i;
        if (pres[v]) {
            rank[v] = run;
            list[run] = v;
            out_b[run] = (float)batch_in[v];
            run++;
        }
    }
    for (int i = 0; i < 64; i++) {
        int p = base + i;
        if (p >= total) out_b[p] = -1.0f;
    }
    if (t == 1023) *cnt = total;
}

__global__ void k_gather_x(const float* __restrict__ h, float* __restrict__ out) {
    int gid = blockIdx.x * blockDim.x + threadIdx.x;
    int which = blockIdx.y;
    if (gid >= NN * 64) return;
    int row = gid >> 6;
    int c = gid & 63;
    int cnt = which ? g_cnt_f : g_cnt_c;
    float4 v;
    if (row < cnt) {
        int src = which ? g_list_f[row] : g_list_c[row];
        v = ((const float4*)h)[(size_t)src * 64 + c];
    } else {
        v = make_float4(0.f, 0.f, 0.f, 0.f);
    }
    float* outx = out + (which ? OFF_FX : OFF_CX);
    ((float4*)outx)[gid] = v;
}

__global__ void k_ei_rel(float* __restrict__ out) {
    int k = blockIdx.x * blockDim.x + threadIdx.x;
    int which = blockIdx.y;
    if (k < 2 * EC) {
        const int* eib = which ? g_fei : g_cei;
        const int* rank = which ? g_rank_f : g_rank_c;
        float* dst = out + (which ? OFF_FEI : OFF_CEI);
        dst[k] = (float)rank[eib[k]];
    }
}

// tail: restore zero-state invariant for next graph replay
__global__ void k_rezero() {
    int i = blockIdx.x * blockDim.x + threadIdx.x;
    if (i <= NN) g_deg[i] = 0;
    if (i < NN) { g_pres_c[i] = 0; g_pres_f[i] = 0; }
}

// ---------------- launch ----------------
extern "C" void kernel_launch(void* const* d_in, const int* in_sizes, int n_in,
                              void* d_out, int out_size) {
    (void)in_sizes; (void)n_in; (void)out_size;
    const float* x    = (const float*)d_in[0];
    const int*   ei   = (const int*)d_in[1];
    const int*   batch= (const int*)d_in[2];
    const float* W11  = (const float*)d_in[3];
    const float* b11  = (const float*)d_in[4];
    const float* W12  = (const float*)d_in[5];
    const float* b12  = (const float*)d_in[6];
    const float* W21  = (const float*)d_in[7];
    const float* b21  = (const float*)d_in[8];
    const float* W22  = (const float*)d_in[9];
    const float* b22  = (const float*)d_in[10];
    const float* wsc  = (const float*)d_in[11];
    const float* bsc  = (const float*)d_in[12];
    float* out = (float*)d_out;

    k_count_deg<<<ET / 256, 256>>>(ei);                      // 0
    k_scan_deg<<<1, 1024>>>();                               // 1
    k_fill_csr<<<ET / 256, 256>>>(ei);                       // 2

    // launch 3: full-wave GEMM PROBE (296 blocks = 1 wave at 2 CTA/SM).
    // Deterministic; writes a prefix of g_u which the real layer-1 GEMM
    // fully overwrites below.
    k_gemm_bias_relu<<<dim3(148, 2), 256>>>(x, W11, b11, g_u);   // 3 <- ncu

    dim3 ggrid(NN / BM, HIDD / BN);

    k_agg<<<NN * 32 / 256, 256>>>(x, g_t);                   // 4
    k_gemm_bias_relu<<<ggrid, 256>>>(g_t, W11, b11, g_u);    // 5
    k_gemm_bias_relu<<<ggrid, 256>>>(g_u, W12, b12, g_h);    // 6

    k_agg<<<NN * 32 / 256, 256>>>(g_h, g_t);                 // 7
    k_gemm_bias_relu<<<ggrid, 256>>>(g_t, W21, b21, g_u);    // 8
    k_gemm_bias_relu<<<ggrid, 256>>>(g_u, W22, b22, g_h);    // 9

    k_score<<<(NN * 32) / 256, 256>>>(g_h, wsc);             // 10
    k_edge_score<<<ET / 256, 256>>>(ei, bsc, out);           // 11

    k_sort_select<<<BB, 1024>>>(out + OFF_ES, ei, out);      // 12

    k_compact<<<2, 1024>>>(batch, out);                      // 13
    k_gather_x<<<dim3((NN * 64) / 256, 2), 256>>>(g_h, out); // 14
    k_ei_rel<<<dim3((2 * EC) / 256, 2), 256>>>(out);         // 15

    k_rezero<<<(NN + 256) / 256, 256>>>();                   // 16
}

// round 8
// speedup vs baseline: 1.0756x; 1.0756x over previous
#include <cuda_runtime.h>
#include <cuda_bf16.h>

typedef unsigned long long ull;

// ---------------- problem constants ----------------
#define NN    65536
#define HIDD  256
#define BB    64
#define EPER  8192
#define ET    524288
#define NRES  4096
#define EC    262144

// ---------------- output offsets (float32 elements) ----------------
#define OFF_CX   0ul
#define OFF_CEI  16777216ul
#define OFF_CW   17301504ul
#define OFF_CB   17563648ul
#define OFF_FX   17629184ul
#define OFF_FEI  34406400ul
#define OFF_FW   34930688ul
#define OFF_FB   35192832ul
#define OFF_ES   35258368ul

// ---------------- scratch (zero-initialized at module load) ----------------
__device__ float g_t[NN * HIDD];
__device__ float g_u[NN * HIDD];
__device__ float g_h[NN * HIDD];
__device__ int   g_deg[NN + 1];   // 0 at entry; re-zeroed at tail
__device__ int   g_pos[NN];
__device__ int   g_col[ET];
__device__ float g_ssrc[NN];
__device__ float g_sdst[NN];
__device__ int   g_cei[2 * EC];
__device__ int   g_fei[2 * EC];
__device__ int   g_pres_c[NN];    // 0 at entry; re-zeroed at tail
__device__ int   g_pres_f[NN];
__device__ int   g_rank_c[NN];
__device__ int   g_rank_f[NN];
__device__ int   g_list_c[NN];
__device__ int   g_list_f[NN];
__device__ int   g_cnt_c;
__device__ int   g_cnt_f;

// ---------------- CSR build ----------------
__global__ void k_count_deg(const int* __restrict__ ei) {
    int e = blockIdx.x * blockDim.x + threadIdx.x;
    if (e < ET) atomicAdd(&g_deg[ei[e] + 1], 1);
}

__global__ __launch_bounds__(1024) void k_scan_deg() {
    __shared__ int part[1024];
    const int t = threadIdx.x;
    const int CH = 65;
    int base = t * CH;
    int n = 0;
    if (base < NN + 1) { n = NN + 1 - base; if (n > CH) n = CH; }
    int s = 0;
    for (int i = 0; i < n; i++) s += g_deg[base + i];
    part[t] = s;
    __syncthreads();
    for (int off = 1; off < 1024; off <<= 1) {
        int v = (t >= off) ? part[t - off] : 0;
        __syncthreads();
        part[t] += v;
        __syncthreads();
    }
    int run = part[t] - s;
    for (int i = 0; i < n; i++) {
        run += g_deg[base + i];
        g_deg[base + i] = run;
        if (base + i < NN) g_pos[base + i] = run;
    }
}

__global__ void k_fill_csr(const int* __restrict__ ei) {
    int e = blockIdx.x * blockDim.x + threadIdx.x;
    if (e < ET) {
        int r = ei[e];
        int p = atomicAdd(&g_pos[r], 1);
        g_col[p] = ei[ET + e];
    }
}

// ---------------- aggregation: block = 2 nodes, 64 lanes/node (measured 398us) ----------------
__global__ __launch_bounds__(128) void k_agg(const float* __restrict__ hin,
                                             float* __restrict__ tout) {
    int v = blockIdx.x * 2 + (threadIdx.x >> 6);
    int lane = threadIdx.x & 63;
    const float4* H = (const float4*)hin;
    float4 acc = H[(size_t)v * 64 + lane];
    int s = g_deg[v], e = g_deg[v + 1];
    int i = s;
    for (; i + 4 <= e; i += 4) {
        int n0 = g_col[i], n1 = g_col[i + 1], n2 = g_col[i + 2], n3 = g_col[i + 3];
        float4 x0 = H[(size_t)n0 * 64 + lane];
        float4 x1 = H[(size_t)n1 * 64 + lane];
        float4 x2 = H[(size_t)n2 * 64 + lane];
        float4 x3 = H[(size_t)n3 * 64 + lane];
        acc.x += x0.x + x1.x + x2.x + x3.x;
        acc.y += x0.y + x1.y + x2.y + x3.y;
        acc.z += x0.z + x1.z + x2.z + x3.z;
        acc.w += x0.w + x1.w + x2.w + x3.w;
    }
    for (; i < e; i++) {
        int nb = g_col[i];
        float4 x = H[(size_t)nb * 64 + lane];
        acc.x += x.x; acc.y += x.y; acc.z += x.z; acc.w += x.w;
    }
    ((float4*)tout)[(size_t)v * 64 + lane] = acc;
}

// ---------------- GEMM: C = relu(A @ W + bias)  (measured 176us/wave) ----------------
#define BM 128
#define BN 128
#define BK 8

__global__ __launch_bounds__(256, 2) void k_gemm_bias_relu(const float* __restrict__ A,
                                                           const float* __restrict__ W,
                                                           const float* __restrict__ bias,
                                                           float* __restrict__ C) {
    __shared__ float As[2][BK][BM];
    __shared__ float Bs[2][BK][BN];

    const int t  = threadIdx.x;
    const int bm = blockIdx.x;
    const int bn = blockIdx.y;
    const int a_row = t >> 1,  a_k   = (t & 1) * 4;
    const int b_row = t >> 5,  b_col = (t & 31) * 4;
    const int tx = t & 15, ty = t >> 4;

    const float* Ab = A + (size_t)bm * BM * 256;
    const float* Wb = W + bn * BN;

    float acc[8][8];
#pragma unroll
    for (int m = 0; m < 8; m++)
#pragma unroll
        for (int n = 0; n < 8; n++) acc[m][n] = 0.f;

    float4 ra = *(const float4*)&Ab[(size_t)a_row * 256 + a_k];
    float4 rb = *(const float4*)&Wb[(size_t)b_row * 256 + b_col];
    As[0][a_k + 0][a_row] = ra.x;
    As[0][a_k + 1][a_row] = ra.y;
    As[0][a_k + 2][a_row] = ra.z;
    As[0][a_k + 3][a_row] = ra.w;
    *(float4*)&Bs[0][b_row][b_col] = rb;
    __syncthreads();

    for (int kt = 0; kt < 32; kt++) {
        const int cur = kt & 1, nxt = cur ^ 1;
        if (kt < 31) {
            int k0 = (kt + 1) * BK;
            ra = *(const float4*)&Ab[(size_t)a_row * 256 + k0 + a_k];
            rb = *(const float4*)&Wb[(size_t)(k0 + b_row) * 256 + b_col];
        }
#pragma unroll
        for (int k = 0; k < BK; k++) {
            float4 a0 = *(const float4*)&As[cur][k][ty * 4];
            float4 a1 = *(const float4*)&As[cur][k][64 + ty * 4];
            float4 b0 = *(const float4*)&Bs[cur][k][tx * 4];
            float4 b1 = *(const float4*)&Bs[cur][k][64 + tx * 4];
            float av[8] = {a0.x, a0.y, a0.z, a0.w, a1.x, a1.y, a1.z, a1.w};
            float bv[8] = {b0.x, b0.y, b0.z, b0.w, b1.x, b1.y, b1.z, b1.w};
#pragma unroll
            for (int m = 0; m < 8; m++)
#pragma unroll
                for (int n = 0; n < 8; n++) acc[m][n] += av[m] * bv[n];
        }
        if (kt < 31) {
            As[nxt][a_k + 0][a_row] = ra.x;
            As[nxt][a_k + 1][a_row] = ra.y;
            As[nxt][a_k + 2][a_row] = ra.z;
            As[nxt][a_k + 3][a_row] = ra.w;
            *(float4*)&Bs[nxt][b_row][b_col] = rb;
        }
        __syncthreads();
    }

    float4 bv0 = *(const float4*)&bias[bn * BN + tx * 4];
    float4 bv1 = *(const float4*)&bias[bn * BN + 64 + tx * 4];
#pragma unroll
    for (int m = 0; m < 8; m++) {
        int row = bm * BM + ((m < 4) ? (ty * 4 + m) : (64 + ty * 4 + m - 4));
        float4 r0, r1;
        r0.x = fmaxf(acc[m][0] + bv0.x, 0.f);
        r0.y = fmaxf(acc[m][1] + bv0.y, 0.f);
        r0.z = fmaxf(acc[m][2] + bv0.z, 0.f);
        r0.w = fmaxf(acc[m][3] + bv0.w, 0.f);
        r1.x = fmaxf(acc[m][4] + bv1.x, 0.f);
        r1.y = fmaxf(acc[m][5] + bv1.y, 0.f);
        r1.z = fmaxf(acc[m][6] + bv1.z, 0.f);
        r1.w = fmaxf(acc[m][7] + bv1.w, 0.f);
        *(float4*)&C[(size_t)row * 256 + bn * BN + tx * 4] = r0;
        *(float4*)&C[(size_t)row * 256 + bn * BN + 64 + tx * 4] = r1;
    }
}

// ---------------- scores ----------------
__global__ __launch_bounds__(256) void k_score(const float* __restrict__ h,
                                               const float* __restrict__ wsc) {
    int gw = (blockIdx.x * blockDim.x + threadIdx.x) >> 5;
    int lane = threadIdx.x & 31;
    if (gw >= NN) return;
    const float4* H = (const float4*)(h + (size_t)gw * 256);
    const float4* W1 = (const float4*)wsc;
    const float4* W2 = (const float4*)(wsc + 256);
    float s1 = 0.f, s2 = 0.f;
#pragma unroll
    for (int i = lane; i < 64; i += 32) {
        float4 hv = H[i], w1 = W1[i], w2 = W2[i];
        s1 += hv.x * w1.x + hv.y * w1.y + hv.z * w1.z + hv.w * w1.w;
        s2 += hv.x * w2.x + hv.y * w2.y + hv.z * w2.z + hv.w * w2.w;
    }
#pragma unroll
    for (int o = 16; o; o >>= 1) {
        s1 += __shfl_xor_sync(0xffffffffu, s1, o);
        s2 += __shfl_xor_sync(0xffffffffu, s2, o);
    }
    if (lane == 0) { g_ssrc[gw] = s1; g_sdst[gw] = s2; }
}

__global__ void k_edge_score(const int* __restrict__ ei,
                             const float* __restrict__ bsc,
                             float* __restrict__ out) {
    int e = blockIdx.x * blockDim.x + threadIdx.x;
    if (e < ET) {
        out[OFF_ES + e] = g_ssrc[ei[e]] + g_sdst[ei[ET + e]] + bsc[0];
    }
}

// ---------------- per-batch stable sort + split ----------------
// Proven shell (3 args, direct global refs, static 48KB split keys).
// NEW: pair-indexed inner loop — each thread does exactly 4 useful
// compare-exchanges per pass (vs 8 half-wasted strided iterations).
__global__ __launch_bounds__(1024) void k_sort_select(const float* __restrict__ es,
                                                      const int* __restrict__ ei,
                                                      float* __restrict__ out) {
    __shared__ unsigned int   kh[EPER];   // 32 KB
    __shared__ unsigned short kl[EPER];   // 16 KB
    const int b = blockIdx.x;
    const int tid = threadIdx.x;

    for (int i = tid; i < EPER; i += 1024) {
        unsigned u = __float_as_uint(es[b * EPER + i]);
        u = (u & 0x80000000u) ? ~u : (u | 0x80000000u);  // ascending-orderable
        kh[i] = ~u;                                       // asc kh == desc score
        kl[i] = (unsigned short)i;                        // tie-break: idx asc
    }
    __syncthreads();

    for (int k = 2; k <= EPER; k <<= 1) {
        for (int j = k >> 1; j > 0; j >>= 1) {
#pragma unroll
            for (int q = 0; q < 4; q++) {
                int p = tid + q * 1024;                    // 4096 disjoint pairs
                int i = ((p & ~(j - 1)) << 1) | (p & (j - 1));
                int l = i | j;
                bool up = ((i & k) == 0);
                unsigned ah = kh[i], bh = kh[l];
                unsigned short al = kl[i], bl = kl[l];
                bool agtb = (ah > bh) || (ah == bh && al > bl);
                if (agtb == up) {
                    kh[i] = bh; kh[l] = ah;
                    kl[i] = bl; kl[l] = al;
                }
            }
            __syncthreads();
        }
    }

    for (int i = tid; i < EPER; i += 1024) {
        int idx = kl[i];
        int ge = b * EPER + idx;
        float s = es[ge];
        int r = ei[ge];
        int c = ei[ET + ge];
        if (i < NRES) {
            int p = b * NRES + i;
            out[OFF_CW + p] = s;
            g_cei[p] = r; g_cei[EC + p] = c;
            g_pres_c[r] = 1; g_pres_c[c] = 1;
        } else {
            int p = b * NRES + (i - NRES);
            out[OFF_FW + p] = -s;
            g_fei[p] = r; g_fei[EC + p] = c;
            g_pres_f[r] = 1; g_pres_f[c] = 1;
        }
    }
}

// ---------------- relabel: compact + batch fill ----------------
__global__ __launch_bounds__(1024) void k_compact(const int* __restrict__ batch_in,
                                                  float* __restrict__ out) {
    __shared__ int part[1024];
    const int which = blockIdx.x;
    const int* pres = which ? g_pres_f : g_pres_c;
    int* rank = which ? g_rank_f : g_rank_c;
    int* list = which ? g_list_f : g_list_c;
    int* cnt = which ? &g_cnt_f : &g_cnt_c;
    float* out_b = out + (which ? OFF_FB : OFF_CB);

    const int t = threadIdx.x;
    const int base = t * 64;
    int s = 0;
    for (int i = 0; i < 64; i++) s += pres[base + i];
    part[t] = s;
    __syncthreads();
    for (int off = 1; off < 1024; off <<= 1) {
        int v = (t >= off) ? part[t - off] : 0;
        __syncthreads();
        part[t] += v;
        __syncthreads();
    }
    int total = part[1023];
    int run = part[t] - s;
    for (int i = 0; i < 64; i++) {
        int v = base + i;
        if (pres[v]) {
            rank[v] = run;
            list[run] = v;
            out_b[run] = (float)batch_in[v];
            run++;
        }
    }
    for (int i = 0; i < 64; i++) {
        int p = base + i;
        if (p >= total) out_b[p] = -1.0f;
    }
    if (t == 1023) *cnt = total;
}

__global__ void k_gather_x(const float* __restrict__ h, float* __restrict__ out) {
    int gid = blockIdx.x * blockDim.x + threadIdx.x;
    int which = blockIdx.y;
    if (gid >= NN * 64) return;
    int row = gid >> 6;
    int c = gid & 63;
    int cnt = which ? g_cnt_f : g_cnt_c;
    float4 v;
    if (row < cnt) {
        int src = which ? g_list_f[row] : g_list_c[row];
        v = ((const float4*)h)[(size_t)src * 64 + c];
    } else {
        v = make_float4(0.f, 0.f, 0.f, 0.f);
    }
    float* outx = out + (which ? OFF_FX : OFF_CX);
    ((float4*)outx)[gid] = v;
}

__global__ void k_ei_rel(float* __restrict__ out) {
    int k = blockIdx.x * blockDim.x + threadIdx.x;
    int which = blockIdx.y;
    if (k < 2 * EC) {
        const int* eib = which ? g_fei : g_cei;
        const int* rank = which ? g_rank_f : g_rank_c;
        float* dst = out + (which ? OFF_FEI : OFF_CEI);
        dst[k] = (float)rank[eib[k]];
    }
}

// tail: restore zero-state invariant for next graph replay
__global__ void k_rezero() {
    int i = blockIdx.x * blockDim.x + threadIdx.x;
    if (i <= NN) g_deg[i] = 0;
    if (i < NN) { g_pres_c[i] = 0; g_pres_f[i] = 0; }
}

// ---------------- launch ----------------
extern "C" void kernel_launch(void* const* d_in, const int* in_sizes, int n_in,
                              void* d_out, int out_size) {
    (void)in_sizes; (void)n_in; (void)out_size;
    const float* x    = (const float*)d_in[0];
    const int*   ei   = (const int*)d_in[1];
    const int*   batch= (const int*)d_in[2];
    const float* W11  = (const float*)d_in[3];
    const float* b11  = (const float*)d_in[4];
    const float* W12  = (const float*)d_in[5];
    const float* b12  = (const float*)d_in[6];
    const float* W21  = (const float*)d_in[7];
    const float* b21  = (const float*)d_in[8];
    const float* W22  = (const float*)d_in[9];
    const float* b22  = (const float*)d_in[10];
    const float* wsc  = (const float*)d_in[11];
    const float* bsc  = (const float*)d_in[12];
    float* out = (float*)d_out;

    k_count_deg<<<ET / 256, 256>>>(ei);                      // 0
    k_scan_deg<<<1, 1024>>>();                               // 1
    k_fill_csr<<<ET / 256, 256>>>(ei);                       // 2

    dim3 ggrid(NN / BM, HIDD / BN);

    k_agg<<<NN / 2, 128>>>(x, g_t);                          // 3
    k_gemm_bias_relu<<<ggrid, 256>>>(g_t, W11, b11, g_u);    // 4
    k_gemm_bias_relu<<<ggrid, 256>>>(g_u, W12, b12, g_h);    // 5

    k_agg<<<NN / 2, 128>>>(g_h, g_t);                        // 6
    k_gemm_bias_relu<<<ggrid, 256>>>(g_t, W21, b21, g_u);    // 7
    k_gemm_bias_relu<<<ggrid, 256>>>(g_u, W22, b22, g_h);    // 8

    k_score<<<(NN * 32) / 256, 256>>>(g_h, wsc);             // 9
    k_edge_score<<<ET / 256, 256>>>(ei, bsc, out);           // 10

    k_sort_select<<<BB, 1024>>>(out + OFF_ES, ei, out);      // 11

    k_compact<<<2, 1024>>>(batch, out);                      // 12
    k_gather_x<<<dim3((NN * 64) / 256, 2), 256>>>(g_h, out); // 13
    k_ei_rel<<<dim3((2 * EC) / 256, 2), 256>>>(out);         // 14

    k_rezero<<<(NN + 256) / 256, 256>>>();                   // 15
}